// round 16
// baseline (speedup 1.0000x reference)
#include <cuda_runtime.h>
#include <cuda_fp16.h>
#include <cstdint>

#define NTH    512
#define NCTA   128
#define TSTEPS 128

// ---- SMEM byte offsets ----
// frags: 580 x 256 B. ids: lay*192 + (isWh?96:0) + nt*4 + kt  (lay0-Wi = fused M),
//        out frags at 576..579
#define OFF_FRAG 0
#define OFF_OUTF (576 * 256)          // 147456
#define OFF_SLOTS 148480              // 8 slots x 8192 B (fp16 SW128, 64 rows each)
#define OFF_BR   214016               // 3 x 64 f32
#define OFF_BZ   214784
#define OFF_BIN  215552
#define OFF_BHN  216320
#define OFF_BO   217088               // 2 f32
#define OFF_BE_T 217096               // 64 f32 (temp, staging only)
#define SMEM_SZ  217408

#define SWZ(o) ((uint32_t)(o) ^ ((((uint32_t)(o)) >> 3) & 0x70u))

static __device__ __forceinline__ uint32_t smem_u32(const void* p) {
    uint32_t a;
    asm("{ .reg .u64 t; cvta.to.shared.u64 t, %1; cvt.u32.u64 %0, t; }" : "=r"(a) : "l"(p));
    return a;
}
static __device__ __forceinline__ void ldmA(uint32_t* a, uint32_t addr) {
    asm volatile("ldmatrix.sync.aligned.m8n8.x4.shared.b16 {%0,%1,%2,%3}, [%4];"
                 : "=r"(a[0]), "=r"(a[1]), "=r"(a[2]), "=r"(a[3]) : "r"(addr));
}
static __device__ __forceinline__ uint2 ldB(uint32_t a) {
    uint2 r;
    asm volatile("ld.shared.v2.b32 {%0,%1}, [%2];" : "=r"(r.x), "=r"(r.y) : "r"(a));
    return r;
}
static __device__ __forceinline__ void mma16816(float* c, const uint32_t* a, uint2 b) {
    asm volatile(
        "mma.sync.aligned.m16n8k16.row.col.f32.f16.f16.f32 "
        "{%0,%1,%2,%3}, {%4,%5,%6,%7}, {%8,%9}, {%0,%1,%2,%3};"
        : "+f"(c[0]), "+f"(c[1]), "+f"(c[2]), "+f"(c[3])
        : "r"(a[0]), "r"(a[1]), "r"(a[2]), "r"(a[3]), "r"(b.x), "r"(b.y));
}
static __device__ __forceinline__ uint32_t packh2(float a, float b) {
    __half2 h = __floats2half2_rn(a, b);
    return *(uint32_t*)&h;
}
static __device__ __forceinline__ float tanha(float x) {
    float y; asm("tanh.approx.f32 %0, %1;" : "=f"(y) : "f"(x)); return y;
}
static __device__ __forceinline__ float sigm(float x) {
    return __fmaf_rn(0.5f, tanha(0.5f * x), 0.5f);
}
static __device__ __forceinline__ float gru1(float rp, float zp, float ni, float nh, float ho) {
    float r = sigm(rp);
    float z = sigm(zp);
    float n = tanha(__fmaf_rn(r, nh, ni));
    return __fmaf_rn(z, ho - n, n);
}
static __device__ __forceinline__ void barG(uint32_t id) {
    asm volatile("bar.sync %0, %1;" :: "r"(id), "r"(256u) : "memory");
}

__global__ void __launch_bounds__(NTH, 1)
futuretraj_kernel(const float* __restrict__ enc,
                  const float* __restrict__ emb_w, const float* __restrict__ emb_b,
                  const float* __restrict__ w_ih,  const float* __restrict__ w_hh,
                  const float* __restrict__ b_ih,  const float* __restrict__ b_hh,
                  const float* __restrict__ out_w, const float* __restrict__ out_b,
                  float* __restrict__ out) {
    extern __shared__ char smem[];
    const uint32_t sb = smem_u32(smem);
    const int tid = threadIdx.x;
    const int ln  = tid & 31;
    const int w   = tid >> 5;
    const int mg  = w >> 3;                   // m-group: rows [mg*64, mg*64+64)
    const int nj  = w & 7;                    // hidden cols 8nj..8nj+7
    const int g   = ln >> 2;
    const int tq  = ln & 3;
    const uint32_t rl = (uint32_t)((ln & 7) + ((ln >> 3) & 1) * 8);
    const uint32_t ub = (uint32_t)((ln >> 4) & 1);
    const uint32_t xr = (uint32_t)(ln & 7);
    const int row0 = blockIdx.x * 128;
    const uint32_t bid = (uint32_t)(1 + mg);

    // ================= staging pass 1: We (fp32) + biases + non-L0-Wi frags ======
    // We temp occupies slots 0-1 (16 KB), be at OFF_BE_T.
    for (int i = tid; i < 64 * 64; i += NTH)
        ((float*)(smem + OFF_SLOTS))[i] = emb_w[i];
    for (int i = tid; i < 64; i += NTH)
        ((float*)(smem + OFF_BE_T))[i] = emb_b[i];
    for (int i = tid; i < 3 * 64; i += NTH) {
        int lay = i >> 6, c = i & 63;
        ((float*)(smem + OFF_BR))[i]  = b_ih[lay * 192 + c]       + b_hh[lay * 192 + c];
        ((float*)(smem + OFF_BZ))[i]  = b_ih[lay * 192 + 64 + c]  + b_hh[lay * 192 + 64 + c];
        ((float*)(smem + OFF_BIN))[i] = b_ih[lay * 192 + 128 + c];
        ((float*)(smem + OFF_BHN))[i] = b_hh[lay * 192 + 128 + c];
    }
    if (tid < 2) ((float*)(smem + OFF_BO))[tid] = out_b[tid];
    // frags f in [96,576) (lay0 Wh, lay1/2 Wi+Wh) and out frags 576..579
    for (int i = tid; i < 484 * 32; i += NTH) {
        int f = 96 + (i >> 5), la = i & 31;
        int gq = la >> 2, tt = la & 3;
        float v0 = 0.f, v1 = 0.f, v2 = 0.f, v3 = 0.f;
        if (f < 576) {
            int lay = f / 192, r = f % 192;
            const float* W = (r >= 96) ? w_hh : w_ih;
            int q = r % 96;
            int nt = q >> 2, kt = q & 3;
            const float* p = W + (size_t)lay * 192 * 64 + (nt * 8 + gq) * 64 + kt * 16 + 2 * tt;
            v0 = p[0]; v1 = p[1]; v2 = p[8]; v3 = p[9];
        } else {
            int kt = f - 576;
            if (gq < 2) {
                const float* p = out_w + gq * 64 + kt * 16 + 2 * tt;
                v0 = p[0]; v1 = p[1]; v2 = p[8]; v3 = p[9];
            }
        }
        uint32_t* d = (uint32_t*)(smem + OFF_FRAG + f * 256 + la * 8);
        d[0] = packh2(v0, v1);
        d[1] = packh2(v2, v3);
    }
    __syncthreads();

    // ============ staging pass 2: fused M = Wi0 @ We frags + bias fold ==========
    for (int s = tid; s < 768; s += NTH) {
        int gg = s >> 2, kt = s & 3;
        const float* wi = w_ih + gg * 64;
        const float4* weB = (const float4*)(smem + OFF_SLOTS);
        float acc[16];
#pragma unroll
        for (int q = 0; q < 16; q++) acc[q] = 0.f;
        float bacc = 0.f;
        const float* beS = (const float*)(smem + OFF_BE_T);
#pragma unroll 4
        for (int e = 0; e < 64; e++) {
            float wv = wi[e];
            const float4* wr = weB + e * 16 + kt * 4;
            float4 a0 = wr[0], a1 = wr[1], a2 = wr[2], a3 = wr[3];
            acc[0]  = __fmaf_rn(wv, a0.x, acc[0]);
            acc[1]  = __fmaf_rn(wv, a0.y, acc[1]);
            acc[2]  = __fmaf_rn(wv, a0.z, acc[2]);
            acc[3]  = __fmaf_rn(wv, a0.w, acc[3]);
            acc[4]  = __fmaf_rn(wv, a1.x, acc[4]);
            acc[5]  = __fmaf_rn(wv, a1.y, acc[5]);
            acc[6]  = __fmaf_rn(wv, a1.z, acc[6]);
            acc[7]  = __fmaf_rn(wv, a1.w, acc[7]);
            acc[8]  = __fmaf_rn(wv, a2.x, acc[8]);
            acc[9]  = __fmaf_rn(wv, a2.y, acc[9]);
            acc[10] = __fmaf_rn(wv, a2.z, acc[10]);
            acc[11] = __fmaf_rn(wv, a2.w, acc[11]);
            acc[12] = __fmaf_rn(wv, a3.x, acc[12]);
            acc[13] = __fmaf_rn(wv, a3.y, acc[13]);
            acc[14] = __fmaf_rn(wv, a3.z, acc[14]);
            acc[15] = __fmaf_rn(wv, a3.w, acc[15]);
            if (kt == 0) bacc = __fmaf_rn(wv, beS[e], bacc);
        }
        int nt = gg >> 3, gq = gg & 7;
        char* fragb = smem + OFF_FRAG + (nt * 4 + kt) * 256;
#pragma unroll
        for (int tt = 0; tt < 4; tt++) {
            *(uint32_t*)(fragb + (gq * 4 + tt) * 8)     = packh2(acc[2 * tt], acc[2 * tt + 1]);
            *(uint32_t*)(fragb + (gq * 4 + tt) * 8 + 4) = packh2(acc[8 + 2 * tt], acc[9 + 2 * tt]);
        }
        if (kt == 0) {
            float* dst = (gg < 64)  ? (float*)(smem + OFF_BR) + gg
                       : (gg < 128) ? (float*)(smem + OFF_BZ) + (gg - 64)
                                    : (float*)(smem + OFF_BIN) + (gg - 128);
            *dst += bacc;
        }
    }
    __syncthreads();

    // ============ staging pass 3: h-init (overwrites We temp) ===================
    for (int i = tid; i < 128 * 64; i += NTH) {
        int r = i >> 6, c = i & 63;
        __half v = __float2half_rn(enc[(size_t)row0 * 64 + i]);
        int sgrp = (r >> 6) * 4;
        uint32_t o = SWZ((uint32_t)(r & 63) * 128u + (uint32_t)c * 2u);
        char* base = smem + OFF_SLOTS + (size_t)sgrp * 8192 + o;
        *(__half*)(base)          = v;   // h0
        *(__half*)(base + 8192)   = v;   // h1
        *(__half*)(base + 16384)  = v;   // h2
    }
    __syncthreads();

    // ---- persistent per-warp constants ----
    const uint32_t fb = sb + OFF_FRAG;
    const uint32_t l8 = (uint32_t)ln * 8u;
    uint2 OUTF[4];
#pragma unroll
    for (int kt = 0; kt < 4; kt++)
        OUTF[kt] = ldB(sb + OFF_OUTF + (uint32_t)kt * 256u + l8);
    const float bo0 = ((const float*)(smem + OFF_BO))[0];
    const float bo1 = ((const float*)(smem + OFF_BO))[1];
    const uint32_t lanerow = rl * 128u;
    const uint32_t stAddr0 = (uint32_t)g * 128u + (uint32_t)((nj ^ g) << 4) + (uint32_t)(4 * tq);
    const int ktho = nj >> 1;
    const int qho  = (nj & 1) << 1;
    const bool outw = (nj < 4);

    // rotation slots (byte offsets): h0, h1, h2, free
    uint32_t s0 = OFF_SLOTS + (uint32_t)(mg * 4 + 0) * 8192u;
    uint32_t s1 = OFF_SLOTS + (uint32_t)(mg * 4 + 1) * 8192u;
    uint32_t s2 = OFF_SLOTS + (uint32_t)(mg * 4 + 2) * 8192u;
    uint32_t sf = OFF_SLOTS + (uint32_t)(mg * 4 + 3) * 8192u;

#pragma unroll 1
    for (int step = 0; step < TSTEPS; step++) {
        uint32_t xsv[3] = {s2, sf, s0};
        uint32_t hsv[3] = {s0, s1, s2};
        uint32_t wdv[3] = {sf, s0, s1};
#pragma unroll 1
        for (int lay = 0; lay < 3; lay++) {
            const uint32_t xs = sb + xsv[lay];
            const uint32_t hs = sb + hsv[lay];
            const uint32_t wdo = wdv[lay];
            const uint32_t wb = fb + (uint32_t)(lay * 192) * 256u + l8;
            uint2 WIR[4], WIZ[4], WIN[4], WHR[4], WHZ[4], WHN[4];
#pragma unroll
            for (int kt = 0; kt < 4; kt++) {
                WIR[kt] = ldB(wb + (uint32_t)(nj * 4 + kt) * 256u);
                WIZ[kt] = ldB(wb + (uint32_t)((nj + 8) * 4 + kt) * 256u);
                WIN[kt] = ldB(wb + (uint32_t)((nj + 16) * 4 + kt) * 256u);
                WHR[kt] = ldB(wb + (uint32_t)(96 + nj * 4 + kt) * 256u);
                WHZ[kt] = ldB(wb + (uint32_t)(96 + (nj + 8) * 4 + kt) * 256u);
                WHN[kt] = ldB(wb + (uint32_t)(96 + (nj + 16) * 4 + kt) * 256u);
            }
            const int bix = lay * 64 + 8 * nj + 2 * tq;
            const float br0 = ((const float*)(smem + OFF_BR))[bix];
            const float br1 = ((const float*)(smem + OFF_BR))[bix + 1];
            const float bz0 = ((const float*)(smem + OFF_BZ))[bix];
            const float bz1 = ((const float*)(smem + OFF_BZ))[bix + 1];
            const float bi0 = ((const float*)(smem + OFF_BIN))[bix];
            const float bi1 = ((const float*)(smem + OFF_BIN))[bix + 1];
            const float bh0 = ((const float*)(smem + OFF_BHN))[bix];
            const float bh1 = ((const float*)(smem + OFF_BHN))[bix + 1];
            const bool douti = (lay == 0) && outw;

#pragma unroll 1
            for (int m = 0; m < 4; m++) {
                const uint32_t xb = xs + (uint32_t)m * 2048u + lanerow;
                const uint32_t hb = hs + (uint32_t)m * 2048u + lanerow;
                float cr[4] = {br0, br1, br0, br1};
                float cz[4] = {bz0, bz1, bz0, bz1};
                float ci[4] = {bi0, bi1, bi0, bi1};
                float ch[4] = {bh0, bh1, bh0, bh1};
                float co[4] = {bo0, bo1, bo0, bo1};
                uint32_t ho0 = 0, ho1 = 0;
                const bool dom = douti && (m == nj);
#pragma unroll
                for (int kt = 0; kt < 4; kt++) {
                    const uint32_t koff = (((((uint32_t)kt << 1) | ub)) ^ xr) * 16u;
                    uint32_t ax[4], ah[4];
                    ldmA(ax, xb + koff);
                    ldmA(ah, hb + koff);
                    mma16816(cr, ax, WIR[kt]);
                    mma16816(cz, ax, WIZ[kt]);
                    mma16816(ci, ax, WIN[kt]);
                    mma16816(ch, ah, WHN[kt]);
                    mma16816(cr, ah, WHR[kt]);
                    mma16816(cz, ah, WHZ[kt]);
                    if (dom) mma16816(co, ax, OUTF[kt]);
                    if (kt == ktho) { ho0 = ah[qho]; ho1 = ah[qho + 1]; }
                }
                if (dom && step > 0 && tq == 0) {
                    const int mtg = mg * 4 + m;
                    float* o0 = out + ((size_t)(row0 + mtg * 16 + g)) * (TSTEPS * 2)
                                    + (step - 1) * 2;
                    *(float2*)o0 = make_float2(co[0], co[1]);
                    *(float2*)(o0 + 8 * (TSTEPS * 2)) = make_float2(co[2], co[3]);
                }
                float2 f0 = __half22float2(*(__half2*)&ho0);
                float2 f1 = __half22float2(*(__half2*)&ho1);
                float h0 = gru1(cr[0], cz[0], ci[0], ch[0], f0.x);
                float h1 = gru1(cr[1], cz[1], ci[1], ch[1], f0.y);
                float h2 = gru1(cr[2], cz[2], ci[2], ch[2], f1.x);
                float h3 = gru1(cr[3], cz[3], ci[3], ch[3], f1.y);
                uint32_t a = wdo + (uint32_t)m * 2048u + stAddr0;
                *(uint32_t*)(smem + a)         = packh2(h0, h1);
                *(uint32_t*)(smem + a + 1024u) = packh2(h2, h3);
            }
            barG(bid);
        }
        // rotate: (h0,h1,h2,free) <- (free, h0, h1, h2)
        uint32_t t = sf; sf = s2; s2 = s1; s1 = s0; s0 = t;
    }

    // ===== final out (t = 127) from h2 = s2 =====
    if (outw) {
        const uint32_t abase = sb + s2 + (uint32_t)nj * 2048u + lanerow;
        float co[4] = {bo0, bo1, bo0, bo1};
#pragma unroll
        for (int kt = 0; kt < 4; kt++) {
            uint32_t ah[4];
            ldmA(ah, abase + (((((uint32_t)kt << 1) | ub)) ^ xr) * 16u);
            mma16816(co, ah, OUTF[kt]);
        }
        if (tq == 0) {
            const int mtg = mg * 4 + nj;
            float* o0 = out + ((size_t)(row0 + mtg * 16 + g)) * (TSTEPS * 2) + 127 * 2;
            *(float2*)o0 = make_float2(co[0], co[1]);
            *(float2*)(o0 + 8 * (TSTEPS * 2)) = make_float2(co[2], co[3]);
        }
    }
}

extern "C" void kernel_launch(void* const* d_in, const int* in_sizes, int n_in,
                              void* d_out, int out_size) {
    (void)in_sizes; (void)n_in; (void)out_size;
    const float* enc   = (const float*)d_in[0];
    const float* emb_w = (const float*)d_in[1];
    const float* emb_b = (const float*)d_in[2];
    const float* w_ih  = (const float*)d_in[3];
    const float* w_hh  = (const float*)d_in[4];
    const float* b_ih  = (const float*)d_in[5];
    const float* b_hh  = (const float*)d_in[6];
    const float* out_w = (const float*)d_in[7];
    const float* out_b = (const float*)d_in[8];
    float* out = (float*)d_out;

    cudaFuncSetAttribute(futuretraj_kernel,
                         cudaFuncAttributeMaxDynamicSharedMemorySize, SMEM_SZ);
    futuretraj_kernel<<<NCTA, NTH, SMEM_SZ>>>(
        enc, emb_w, emb_b, w_ih, w_hh, b_ih, b_hh, out_w, out_b, out);
}